// round 2
// baseline (speedup 1.0000x reference)
#include <cuda_runtime.h>
#include <math.h>

#define EPSF 1e-6f

// Per-block partial sums. Every used slot is written on every launch, so no
// zeroing kernel is needed and the result is deterministic (no atomics).
__device__ float g_part[8192];

__global__ void finalize_kernel(float* __restrict__ out, int nblocks, float inv_n) {
    double s = 0.0;
    for (int i = threadIdx.x; i < nblocks; i += blockDim.x)
        s += (double)g_part[i];
    #pragma unroll
    for (int o = 16; o > 0; o >>= 1)
        s += __shfl_down_sync(0xffffffffu, s, o);
    __shared__ double ws[8];
    int lane = threadIdx.x & 31, wid = threadIdx.x >> 5;
    if (lane == 0) ws[wid] = s;
    __syncthreads();
    if (wid == 0) {
        double v = (lane < 8) ? ws[lane] : 0.0;
        #pragma unroll
        for (int o = 4; o > 0; o >>= 1)
            v += __shfl_down_sync(0xffffffffu, v, o);
        if (lane == 0) out[0] = (float)(v * (double)inv_n);
    }
}

__global__ __launch_bounds__(256)
void rotated_iou_loss_kernel(const float* __restrict__ pred,
                             const float* __restrict__ target,
                             const float* __restrict__ weight,
                             int n)
{
    int i = blockIdx.x * blockDim.x + threadIdx.x;
    float loss = 0.0f;

    if (i < n) {
        const float* pp = pred + i * 5;
        const float* tp = target + i * 5;
        float p_x = pp[0], p_y = pp[1], p_w = pp[2], p_h = pp[3], p_a = pp[4];
        float t_x = tp[0], t_y = tp[1], t_w = tp[2], t_h = tp[3], t_a = tp[4];

        float ps, pc, ts, tc;
        __sincosf(p_a, &ps, &pc);
        __sincosf(t_a, &ts, &tc);

        const float dxs[4] = { 0.5f, -0.5f, -0.5f,  0.5f };
        const float dys[4] = { 0.5f,  0.5f, -0.5f, -0.5f };
        float c1x[4], c1y[4], c2x[4], c2y[4];
        #pragma unroll
        for (int j = 0; j < 4; j++) {
            float lx = p_w * dxs[j], ly = p_h * dys[j];
            c1x[j] = p_x + lx * pc - ly * ps;
            c1y[j] = p_y + lx * ps + ly * pc;
            lx = t_w * dxs[j]; ly = t_h * dys[j];
            c2x[j] = t_x + lx * tc - ly * ts;
            c2y[j] = t_y + lx * ts + ly * tc;
        }

        // Candidate points in FIXED slots (no compaction -> no serial deps):
        //   0..15  edge intersections (pred-edge-major, matching reference reshape)
        //   16..19 pred corners, 20..23 target corners
        // Invalid slots store exact 0 so they gather as zeros in the shoelace.
        float PX[32], PY[32];
        unsigned vmask = 0u;
        float sx = 0.0f, sy = 0.0f;

        #pragma unroll
        for (int j = 0; j < 4; j++) {
            float p1x = c1x[j], p1y = c1y[j];
            float d1x = c1x[(j + 1) & 3] - p1x;
            float d1y = c1y[(j + 1) & 3] - p1y;
            #pragma unroll
            for (int k = 0; k < 4; k++) {
                int s = j * 4 + k;
                float p2x = c2x[k], p2y = c2y[k];
                float d2x = c2x[(k + 1) & 3] - p2x;
                float d2y = c2y[(k + 1) & 3] - p2y;
                float den = d1x * d2y - d1y * d2x;
                float inv = __fdividef(1.0f, den);
                float rpx = p2x - p1x, rpy = p2y - p1y;
                float tt = (rpx * d2y - rpy * d2x) * inv;
                float uu = (rpx * d1y - rpy * d1x) * inv;
                bool ok = (fabsf(den) > 1e-8f) &&
                          (tt >= 0.0f) && (tt <= 1.0f) &&
                          (uu >= 0.0f) && (uu <= 1.0f);
                float ix = fmaf(tt, d1x, p1x);
                float iy = fmaf(tt, d1y, p1y);
                float mxv = ok ? ix : 0.0f;
                float myv = ok ? iy : 0.0f;
                PX[s] = mxv; PY[s] = myv;
                sx += mxv; sy += myv;
                if (ok) vmask |= (1u << s);
            }
        }

        const float tol = 1e-6f;
        {   // pred corners inside target
            float hw = t_w * 0.5f + tol, hh = t_h * 0.5f + tol;
            #pragma unroll
            for (int j = 0; j < 4; j++) {
                float dx = c1x[j] - t_x, dy = c1y[j] - t_y;
                float u  =  dx * tc + dy * ts;
                float v  = -dx * ts + dy * tc;
                bool ok = (fabsf(u) <= hw) && (fabsf(v) <= hh);
                int s = 16 + j;
                float mxv = ok ? c1x[j] : 0.0f;
                float myv = ok ? c1y[j] : 0.0f;
                PX[s] = mxv; PY[s] = myv;
                sx += mxv; sy += myv;
                if (ok) vmask |= (1u << s);
            }
        }
        {   // target corners inside pred
            float hw = p_w * 0.5f + tol, hh = p_h * 0.5f + tol;
            #pragma unroll
            for (int j = 0; j < 4; j++) {
                float dx = c2x[j] - p_x, dy = c2y[j] - p_y;
                float u  =  dx * pc + dy * ps;
                float v  = -dx * ps + dy * pc;
                bool ok = (fabsf(u) <= hw) && (fabsf(v) <= hh);
                int s = 20 + j;
                float mxv = ok ? c2x[j] : 0.0f;
                float myv = ok ? c2y[j] : 0.0f;
                PX[s] = mxv; PY[s] = myv;
                sx += mxv; sy += myv;
                if (ok) vmask |= (1u << s);
            }
        }
        #pragma unroll
        for (int s = 24; s < 32; s++) { PX[s] = 0.0f; PY[s] = 0.0f; }

        float cntf = fmaxf((float)__popc(vmask), 1.0f);
        float invc = __fdividef(1.0f, cntf);
        float mx = sx * invc, my = sy * invc;

        // Pseudo-angle keys (monotone in atan2), order-preserving uint,
        // low 5 bits = slot index (stable tie-break = original order).
        unsigned keys[32];
        #pragma unroll
        for (int s = 0; s < 24; s++) {
            bool v = (vmask >> s) & 1u;
            float x = PX[s] - mx, y = PY[s] - my;
            float xv = v ? x : 0.0f;
            float yv = v ? y : 0.0f;
            PX[s] = xv; PY[s] = yv;            // rel vectors, zeros for invalid
            float d = fabsf(xv) + fabsf(yv);
            float r = __fdividef(xv, d);
            float pa = (yv >= 0.0f) ? (1.0f - r) : (r - 1.0f);
            pa = (d > 0.0f) ? pa : 0.0f;       // atan2(0,0)=0 convention
            unsigned b = __float_as_uint(pa);
            unsigned okey = ((int)b < 0) ? ~b : (b | 0x80000000u);
            keys[s] = v ? ((okey & 0xFFFFFFE0u) | (unsigned)s)
                        : (0xFFFFFFE0u | (unsigned)s);   // invalid: after all valid
        }
        #pragma unroll
        for (int s = 24; s < 32; s++) keys[s] = 0xFFFFFFFFu;  // padding: last

        // Batcher odd-even mergesort, n=32, register-resident, fully uniform.
        #pragma unroll
        for (int p = 1; p < 32; p <<= 1) {
            #pragma unroll
            for (int k = p; k >= 1; k >>= 1) {
                #pragma unroll
                for (int j = (k & (p - 1)); j + k < 32; j += 2 * k) {
                    #pragma unroll
                    for (int q = 0; q < k; q++) {
                        if (q + j + k < 32) {
                            if ((q + j) / (2 * p) == (q + j + k) / (2 * p)) {
                                unsigned a = keys[q + j], b = keys[q + j + k];
                                keys[q + j]     = min(a, b);
                                keys[q + j + k] = max(a, b);
                            }
                        }
                    }
                }
            }
        }

        // Cyclic shoelace over the 24 sorted slots (zeros for invalid),
        // exactly matching the reference's masked roll semantics.
        float area2 = 0.0f;
        int idx0 = keys[0] & 31;
        float fx = PX[idx0], fy = PY[idx0];
        float prx = fx, pry = fy;
        #pragma unroll
        for (int tq = 1; tq < 24; tq++) {
            int idx = keys[tq] & 31;
            float gx = PX[idx], gy = PY[idx];
            area2 += prx * gy - pry * gx;
            prx = gx; pry = gy;
        }
        area2 += prx * fy - pry * fx;

        float inter = 0.5f * fabsf(area2);
        float uni = p_w * p_h + t_w * t_h - inter;
        float iou = __fdividef(inter, fmaxf(uni, EPSF));
        iou = fmaxf(iou, EPSF);
        loss = (1.0f - iou * iou * iou) * weight[i];
    }

    // Block reduction -> one partial per block (deterministic, no atomics).
    #pragma unroll
    for (int o = 16; o > 0; o >>= 1)
        loss += __shfl_down_sync(0xffffffffu, loss, o);

    __shared__ float warp_sums[8];
    int lane = threadIdx.x & 31;
    int wid  = threadIdx.x >> 5;
    if (lane == 0) warp_sums[wid] = loss;
    __syncthreads();

    if (wid == 0) {
        float v = (lane < 8) ? warp_sums[lane] : 0.0f;
        #pragma unroll
        for (int o = 4; o > 0; o >>= 1)
            v += __shfl_down_sync(0xffffffffu, v, o);
        if (lane == 0) g_part[blockIdx.x] = v;
    }
}

extern "C" void kernel_launch(void* const* d_in, const int* in_sizes, int n_in,
                              void* d_out, int out_size) {
    const float* pred   = (const float*)d_in[0];
    const float* target = (const float*)d_in[1];
    const float* wgt    = (const float*)d_in[2];
    float* out = (float*)d_out;

    int n = in_sizes[2];
    if (n * 5 != in_sizes[0]) n = in_sizes[0] / 5;

    int threads = 256;
    int blocks = (n + threads - 1) / threads;
    if (blocks > 8192) blocks = 8192;   // n=500k -> 1954, safe margin

    rotated_iou_loss_kernel<<<blocks, threads>>>(pred, target, wgt, n);
    finalize_kernel<<<1, 256>>>(out, blocks, 1.0f / (float)n);
}

// round 3
// speedup vs baseline: 1.5058x; 1.5058x over previous
#include <cuda_runtime.h>
#include <math.h>

#define EPSF 1e-6f

__device__ float g_part[4096];
__device__ unsigned int g_ticket;   // zero-initialized; self-resets each launch

__global__ __launch_bounds__(256)
void rotated_iou_loss_kernel(const float* __restrict__ pred,
                             const float* __restrict__ target,
                             const float* __restrict__ weight,
                             float* __restrict__ out,
                             int n, float inv_n)
{
    int i = blockIdx.x * blockDim.x + threadIdx.x;
    float loss = 0.0f;

    if (i < n) {
        const float* pp = pred + i * 5;
        const float* tp = target + i * 5;
        float p_x = pp[0], p_y = pp[1], p_w = pp[2], p_h = pp[3], p_a = pp[4];
        float t_x = tp[0], t_y = tp[1], t_w = tp[2], t_h = tp[3], t_a = tp[4];

        float ps, pc, ts, tc;
        __sincosf(p_a, &ps, &pc);
        __sincosf(t_a, &ts, &tc);

        const float dxs[4] = { 0.5f, -0.5f, -0.5f,  0.5f };
        const float dys[4] = { 0.5f,  0.5f, -0.5f, -0.5f };
        float c1x[4], c1y[4], c2x[4], c2y[4];
        #pragma unroll
        for (int j = 0; j < 4; j++) {
            float lx = p_w * dxs[j], ly = p_h * dys[j];
            c1x[j] = p_x + lx * pc - ly * ps;
            c1y[j] = p_y + lx * ps + ly * pc;
            lx = t_w * dxs[j]; ly = t_h * dys[j];
            c2x[j] = t_x + lx * tc - ly * ts;
            c2y[j] = t_y + lx * ts + ly * tc;
        }

        // Compacted candidate points (order: 16 intersections pred-edge-major,
        // then pred corners, then target corners -> matches reference order).
        float X[24], Y[24];
        int m = 0;
        float sx = 0.0f, sy = 0.0f;

        #pragma unroll
        for (int j = 0; j < 4; j++) {
            float p1x = c1x[j], p1y = c1y[j];
            float d1x = c1x[(j + 1) & 3] - p1x;
            float d1y = c1y[(j + 1) & 3] - p1y;
            #pragma unroll
            for (int k = 0; k < 4; k++) {
                float p2x = c2x[k], p2y = c2y[k];
                float d2x = c2x[(k + 1) & 3] - p2x;
                float d2y = c2y[(k + 1) & 3] - p2y;
                float den = d1x * d2y - d1y * d2x;
                float inv = __fdividef(1.0f, den);
                float rpx = p2x - p1x, rpy = p2y - p1y;
                float tt = (rpx * d2y - rpy * d2x) * inv;
                float uu = (rpx * d1y - rpy * d1x) * inv;
                if (fabsf(den) > 1e-8f &&
                    tt >= 0.0f && tt <= 1.0f && uu >= 0.0f && uu <= 1.0f) {
                    float ix = fmaf(tt, d1x, p1x);
                    float iy = fmaf(tt, d1y, p1y);
                    X[m] = ix; Y[m] = iy;
                    sx += ix; sy += iy;
                    m++;
                }
            }
        }

        const float tol = 1e-6f;
        {   // pred corners inside target
            float hw = t_w * 0.5f + tol, hh = t_h * 0.5f + tol;
            #pragma unroll
            for (int j = 0; j < 4; j++) {
                float dx = c1x[j] - t_x, dy = c1y[j] - t_y;
                float u  =  dx * tc + dy * ts;
                float v  = -dx * ts + dy * tc;
                if (fabsf(u) <= hw && fabsf(v) <= hh) {
                    X[m] = c1x[j]; Y[m] = c1y[j];
                    sx += c1x[j]; sy += c1y[j];
                    m++;
                }
            }
        }
        {   // target corners inside pred
            float hw = p_w * 0.5f + tol, hh = p_h * 0.5f + tol;
            #pragma unroll
            for (int j = 0; j < 4; j++) {
                float dx = c2x[j] - p_x, dy = c2y[j] - p_y;
                float u  =  dx * pc + dy * ps;
                float v  = -dx * ps + dy * pc;
                if (fabsf(u) <= hw && fabsf(v) <= hh) {
                    X[m] = c2x[j]; Y[m] = c2y[j];
                    sx += c2x[j]; sy += c2y[j];
                    m++;
                }
            }
        }

        float cnt = fmaxf((float)m, 1.0f);
        float invc = __fdividef(1.0f, cnt);
        float mx = sx * invc, my = sy * invc;

        // Pseudo-angle (strictly monotone in atan2): cheap substitute for
        // atan2f, already validated within the rel_err budget.
        float ang[24];
        for (int t = 0; t < m; t++) {
            float x = X[t] - mx;
            float y = Y[t] - my;
            X[t] = x; Y[t] = y;
            float d = fabsf(x) + fabsf(y);
            float r = __fdividef(x, d);
            float pa = (y >= 0.0f) ? (1.0f - r) : (r - 1.0f);
            ang[t] = (d > 0.0f) ? pa : 0.0f;
        }

        // Stable insertion sort (average m ~ 4-8 -> cheap in practice).
        for (int a = 1; a < m; a++) {
            float ka = ang[a], kx = X[a], ky = Y[a];
            int b = a - 1;
            while (b >= 0 && ang[b] > ka) {
                ang[b + 1] = ang[b];
                X[b + 1] = X[b];
                Y[b + 1] = Y[b];
                b--;
            }
            ang[b + 1] = ka;
            X[b + 1] = kx;
            Y[b + 1] = ky;
        }

        // Shoelace with reference's masked-roll semantics:
        // wrap term included only when all 24 slots are valid.
        float s = 0.0f;
        for (int t = 0; t + 1 < m; t++)
            s += X[t] * Y[t + 1] - Y[t] * X[t + 1];
        if (m == 24)
            s += X[23] * Y[0] - Y[23] * X[0];

        float inter = 0.5f * fabsf(s);
        float uni = p_w * p_h + t_w * t_h - inter;
        float iou = __fdividef(inter, fmaxf(uni, EPSF));
        iou = fmaxf(iou, EPSF);
        loss = (1.0f - iou * iou * iou) * weight[i];
    }

    // --- block reduction -> per-block partial (deterministic) ---
    #pragma unroll
    for (int o = 16; o > 0; o >>= 1)
        loss += __shfl_down_sync(0xffffffffu, loss, o);

    __shared__ float warp_sums[8];
    __shared__ bool is_last;
    int lane = threadIdx.x & 31;
    int wid  = threadIdx.x >> 5;
    if (lane == 0) warp_sums[wid] = loss;
    __syncthreads();

    if (wid == 0) {
        float v = (lane < 8) ? warp_sums[lane] : 0.0f;
        #pragma unroll
        for (int o = 4; o > 0; o >>= 1)
            v += __shfl_down_sync(0xffffffffu, v, o);
        if (lane == 0) {
            g_part[blockIdx.x] = v;
            __threadfence();
            unsigned int t = atomicAdd(&g_ticket, 1u);
            is_last = (t == gridDim.x - 1);
        }
    }
    __syncthreads();

    // --- last block: final reduction in fixed order (deterministic) ---
    if (is_last) {
        int nb = gridDim.x;
        double s = 0.0;
        for (int b = threadIdx.x; b < nb; b += blockDim.x)
            s += (double)g_part[b];
        #pragma unroll
        for (int o = 16; o > 0; o >>= 1)
            s += __shfl_down_sync(0xffffffffu, s, o);
        __shared__ double dsum[8];
        if (lane == 0) dsum[wid] = s;
        __syncthreads();
        if (wid == 0) {
            double v = (lane < 8) ? dsum[lane] : 0.0;
            #pragma unroll
            for (int o = 4; o > 0; o >>= 1)
                v += __shfl_down_sync(0xffffffffu, v, o);
            if (lane == 0) {
                out[0] = (float)(v * (double)inv_n);
                g_ticket = 0u;   // reset for next graph replay
            }
        }
    }
}

extern "C" void kernel_launch(void* const* d_in, const int* in_sizes, int n_in,
                              void* d_out, int out_size) {
    const float* pred   = (const float*)d_in[0];
    const float* target = (const float*)d_in[1];
    const float* wgt    = (const float*)d_in[2];
    float* out = (float*)d_out;

    int n = in_sizes[2];
    if (n * 5 != in_sizes[0]) n = in_sizes[0] / 5;

    int threads = 256;
    int blocks = (n + threads - 1) / threads;   // 500k -> 1954 (< 4096)

    rotated_iou_loss_kernel<<<blocks, threads>>>(pred, target, wgt, out,
                                                 n, 1.0f / (float)n);
}